// round 8
// baseline (speedup 1.0000x reference)
#include <cuda_runtime.h>

#define BB   128
#define VV   256
#define FF   64
#define NS   4
#define NLR  64
#define NSLR 68
#define KNB  40
#define NOUT 128
#define KOUT 192

// ---------------- scratch ----------------------------------------------------
__device__ float g_mx  [BB * FF];
__device__ float g_s   [BB * VV * NS];
__device__ float g_lr  [BB * VV * NLR];
__device__ int   g_nidx[BB * VV * KNB];
__device__ float g_nw  [BB * VV * KNB];
__device__ float g_bb  [BB * NOUT];               // b_out + mx @ W_out[64:128]
__device__ float g_fpT [BB * KOUT * VV];          // transposed fp: [b][k][v]

// ---------------- packed f32x2 helpers ---------------------------------------
typedef unsigned long long ull;
__device__ __forceinline__ ull pack2(float lo, float hi) {
    ull r; asm("mov.b64 %0, {%1, %2};" : "=l"(r) : "f"(lo), "f"(hi)); return r;
}
__device__ __forceinline__ void unpack2(ull v, float& lo, float& hi) {
    asm("mov.b64 {%0, %1}, %2;" : "=f"(lo), "=f"(hi) : "l"(v));
}
__device__ __forceinline__ void fma2(ull& d, ull a, ull b) {
    asm("fma.rn.f32x2 %0, %1, %2, %0;" : "+l"(d) : "l"(a), "l"(b));
}
__device__ __forceinline__ ull mul2(ull a, ull b) {
    ull r; asm("mul.rn.f32x2 %0, %1, %2;" : "=l"(r) : "l"(a), "l"(b)); return r;
}

// ============ K_FRONT: mean + slr GEMM + out-bias + x-transpose ==============
#define XSP 65
#define KF_SMEM ((VV * XSP + 128 * NSLR + 64 + 256 + NSLR) * 4)
__global__ void k_front(const float* __restrict__ x,
                        const float* __restrict__ W,
                        const float* __restrict__ bias,
                        const float* __restrict__ W_out,
                        const float* __restrict__ b_out) {
    extern __shared__ float sh[];
    float* xs   = sh;                       // [256][65]
    float* Wsh  = xs + VV * XSP;            // [128][68]
    float* mean = Wsh + 128 * NSLR;         // [64]
    float* red  = mean + 64;                // [256]
    float* cc   = red + 256;                // [68]
    int b = blockIdx.x;
    int t = threadIdx.x;

    const float* xb = x + (size_t)b * VV * FF;
    for (int e = t; e < VV * FF; e += 256) {
        int row = e >> 6, c = e & 63;
        xs[row * XSP + c] = xb[e];
    }
    for (int e = t; e < 128 * NSLR; e += 256) Wsh[e] = W[e];
    __syncthreads();

    // x-part of transposed fp: g_fpT[b][k][v] = x[b][v][k], k<64
    {
        float* dst = g_fpT + (size_t)b * KOUT * VV;
        for (int e = t; e < FF * VV; e += 256) {
            int k = e >> 8, v = e & 255;
            dst[e] = xs[v * XSP + k];
        }
    }

    {
        int f = t & 63, vg = t >> 6;
        float acc = 0.f;
        #pragma unroll 8
        for (int v = vg * 64; v < vg * 64 + 64; v++) acc += xs[v * XSP + f];
        red[vg * 64 + f] = acc;
    }
    __syncthreads();
    if (t < 64) {
        float m = (red[t] + red[64 + t] + red[128 + t] + red[192 + t]) * (1.0f / VV);
        mean[t] = m;
        g_mx[b * FF + t] = m;
    }
    __syncthreads();

    if (t < NSLR) {
        float acc = bias[t];
        #pragma unroll 8
        for (int k = 0; k < 64; k++) acc += mean[k] * Wsh[(64 + k) * NSLR + t];
        cc[t] = acc;
    }
    if (t < NOUT) {
        float acc = b_out[t];
        const float* wr = W_out + 64 * NOUT + t;
        #pragma unroll 16
        for (int k = 0; k < 64; k++) acc += mean[k] * wr[k * NOUT];
        g_bb[b * NOUT + t] = acc;
    }
    __syncthreads();

    int rg = t >> 2;
    int cg = t & 3;
    float acc[4][17];
    #pragma unroll
    for (int u = 0; u < 17; u++) {
        float c0 = cc[cg * 17 + u];
        #pragma unroll
        for (int q = 0; q < 4; q++) acc[q][u] = c0;
    }
    const float* xr = xs + (rg * 4) * XSP;
    #pragma unroll 2
    for (int k = 0; k < 64; k++) {
        float a0 = xr[k], a1 = xr[XSP + k], a2 = xr[2 * XSP + k], a3 = xr[3 * XSP + k];
        const float* wrow = Wsh + k * NSLR + cg * 17;
        #pragma unroll
        for (int u = 0; u < 17; u++) {
            float w = wrow[u];
            acc[0][u] += a0 * w; acc[1][u] += a1 * w;
            acc[2][u] += a2 * w; acc[3][u] += a3 * w;
        }
    }
    #pragma unroll
    for (int q = 0; q < 4; q++) {
        int bv = b * VV + rg * 4 + q;
        #pragma unroll
        for (int u = 0; u < 17; u++) {
            int col = cg * 17 + u;
            float v = fmaxf(acc[q][u], 0.f);
            if (col < NS) g_s [bv * NS  + col]       = v;
            else          g_lr[bv * NLR + col - NS]  = v;
        }
    }
}

// ============ K_SEL: warp-per-row top-40 by (d2, idx) ========================
__global__ void k_sel() {
    __shared__ float4 s_sh[VV];
    int b = blockIdx.x >> 5;
    int i = ((blockIdx.x & 31) << 3) + (threadIdx.x >> 5);
    int l = threadIdx.x & 31;
    if (threadIdx.x < VV)
        s_sh[threadIdx.x] = ((const float4*)g_s)[b * VV + threadIdx.x];
    __syncthreads();

    float4 sv = s_sh[i];
    float d2[8]; unsigned bits[8];
    #pragma unroll
    for (int q = 0; q < 8; q++) {
        float4 sj = s_sh[q * 32 + l];
        float dx = sv.x - sj.x, dy = sv.y - sj.y, dz = sv.z - sj.z, dw = sv.w - sj.w;
        d2[q] = dx * dx + dy * dy + dz * dz + dw * dw;
        bits[q] = __float_as_uint(d2[q]);
    }
    unsigned lo = 0u, hi = 0xFFFFFFFFu;
    #pragma unroll 1
    for (int it = 0; it < 32; it++) {
        unsigned mid = lo + ((hi - lo) >> 1);
        int c = 0;
        #pragma unroll
        for (int q = 0; q < 8; q++) c += (bits[q] <= mid);
        c = __reduce_add_sync(0xFFFFFFFFu, c);
        if (c >= KNB) hi = mid; else lo = mid + 1u;
    }
    unsigned thr = lo;
    int cl = 0;
    #pragma unroll
    for (int q = 0; q < 8; q++) cl += (bits[q] < thr);
    cl = __reduce_add_sync(0xFFFFFFFFu, cl);
    int need = KNB - cl;
    int jlo = 0, jhi = VV - 1;
    #pragma unroll 1
    for (int it = 0; it < 8; it++) {
        int jm = (jlo + jhi) >> 1;
        int c = 0;
        #pragma unroll
        for (int q = 0; q < 8; q++) c += (bits[q] == thr && (q * 32 + l) <= jm);
        c = __reduce_add_sync(0xFFFFFFFFu, c);
        if (c >= need) jhi = jm; else jlo = jm + 1;
    }
    int jthr = jlo;

    int row = b * VV + i;
    int base = 0;
    #pragma unroll
    for (int q = 0; q < 8; q++) {
        int j = q * 32 + l;
        bool sel = (bits[q] < thr) || (bits[q] == thr && j <= jthr);
        unsigned bal = __ballot_sync(0xFFFFFFFFu, sel);
        if (sel) {
            int pos = base + __popc(bal & ((1u << l) - 1u));
            g_nidx[row * KNB + pos] = j;
            g_nw  [row * KNB + pos] = __expf(-10.0f * d2[q]);
        }
        base += __popc(bal);
    }
}

// ============ K_AGG: warp-per-row weighted mean/max, conflict-free ===========
// 4 blocks per batch (64 rows each), 256 threads = 8 warps x 8 rows.
// Lane l owns features (2l, 2l+1): gather lr_sh[j*66 + 2l] is a consecutive
// LDS.64 across the warp; idx (pre-scaled to byte offsets) and w broadcast.
#define LRP2 66
#define KA_SMEM ((VV * LRP2 + 64 * KNB * 2) * 4)
__global__ void k_agg() {
    extern __shared__ float sh[];
    float* lr_sh = sh;                        // [256][66]
    int*   soff  = (int*)(sh + VV * LRP2);    // [64][40] byte offsets
    float* swq   = (float*)(soff + 64 * KNB); // [64][40]
    int b = blockIdx.x >> 2;
    int q = blockIdx.x & 3;
    int t = threadIdx.x;
    int w = t >> 5, l = t & 31;

    const float* lrg = g_lr + (size_t)b * VV * NLR;
    for (int e = t; e < VV * NLR; e += 256) {
        int r = e >> 6, c = e & 63;
        lr_sh[r * LRP2 + c] = lrg[e];
    }
    {
        const int*   gi = g_nidx + ((size_t)b * VV + q * 64) * KNB;
        const float* gw = g_nw   + ((size_t)b * VV + q * 64) * KNB;
        for (int e = t; e < 64 * KNB; e += 256) {
            soff[e] = gi[e] * (LRP2 * 4);     // byte offset of row j
            swq [e] = gw[e];
        }
    }
    __syncthreads();

    const char* lrb = (const char*)lr_sh + 8 * l;
    float m0v[8], m1v[8], x0v[8], x1v[8];

    #pragma unroll
    for (int r8 = 0; r8 < 8; r8++) {
        int li = w * 8 + r8;
        const int*   op = soff + li * KNB;
        const float* wp = swq  + li * KNB;
        ull m2 = 0ull;
        float mx0 = 0.f, mx1 = 0.f;
        #pragma unroll 4
        for (int k = 0; k < KNB; k++) {
            int   off = op[k];
            float wk  = wp[k];
            ull w2 = pack2(wk, wk);
            ull v  = *(const ull*)(lrb + off);
            fma2(m2, v, w2);
            ull vw = mul2(v, w2);
            float p0, p1; unpack2(vw, p0, p1);
            mx0 = fmaxf(mx0, p0);
            mx1 = fmaxf(mx1, p1);
        }
        float s0, s1; unpack2(m2, s0, s1);
        m0v[r8] = s0 * (1.0f / KNB);
        m1v[r8] = s1 * (1.0f / KNB);
        x0v[r8] = mx0;
        x1v[r8] = mx1;
    }

    // stores: feature f at g_fpT[b][64+f][i] (mean), [128+f][i] (max)
    int i0 = q * 64 + w * 8;                  // 8 consecutive rows, 32B aligned
    float* basep = g_fpT + (size_t)b * KOUT * VV;
    float* dm0 = basep + (size_t)(64  + 2 * l)     * VV + i0;
    float* dm1 = basep + (size_t)(64  + 2 * l + 1) * VV + i0;
    float* dx0 = basep + (size_t)(128 + 2 * l)     * VV + i0;
    float* dx1 = basep + (size_t)(128 + 2 * l + 1) * VV + i0;
    *(float4*)(dm0)     = make_float4(m0v[0], m0v[1], m0v[2], m0v[3]);
    *(float4*)(dm0 + 4) = make_float4(m0v[4], m0v[5], m0v[6], m0v[7]);
    *(float4*)(dm1)     = make_float4(m1v[0], m1v[1], m1v[2], m1v[3]);
    *(float4*)(dm1 + 4) = make_float4(m1v[4], m1v[5], m1v[6], m1v[7]);
    *(float4*)(dx0)     = make_float4(x0v[0], x0v[1], x0v[2], x0v[3]);
    *(float4*)(dx0 + 4) = make_float4(x0v[4], x0v[5], x0v[6], x0v[7]);
    *(float4*)(dx1)     = make_float4(x1v[0], x1v[1], x1v[2], x1v[3]);
    *(float4*)(dx1 + 4) = make_float4(x1v[4], x1v[5], x1v[6], x1v[7]);
}

// ============ K_OUT: out = relu(fpT^T @ W + bb) ==============================
// 32 rows x 128 cols per block, 1024 blocks, 128 threads.
// Thread tile: 8 rows (4 f32x2 pairs) x 4 cols = 16 fma2 per k.
#define ROWS_O 32
#define KO_SMEM ((KOUT * ROWS_O + NOUT) * 4)
__global__ void k_out(const float* __restrict__ W,
                      float* __restrict__ out) {
    extern __shared__ float sh[];
    float* fs  = sh;                     // [192][32]
    float* bbs = fs + KOUT * ROWS_O;     // [128]
    int t   = threadIdx.x;
    int bv0 = blockIdx.x * ROWS_O;
    int b   = bv0 >> 8;

    const float* src = g_fpT + (size_t)b * KOUT * VV + (bv0 & 255);
    #pragma unroll 12
    for (int e = t; e < KOUT * ROWS_O; e += 128) {
        int k = e >> 5, r = e & 31;
        fs[e] = src[k * VV + r];
    }
    bbs[t] = g_bb[b * NOUT + t];
    __syncthreads();

    int rg = t >> 5;     // 4 rowgroups x 8 rows
    int cg = t & 31;     // 32 colgroups x 4 cols

    ull acc[4][4];       // [rowpair][col]
    #pragma unroll
    for (int c = 0; c < 4; c++) {
        float bv = bbs[cg * 4 + c];
        ull bp = pack2(bv, bv);
        #pragma unroll
        for (int rp = 0; rp < 4; rp++) acc[rp][c] = bp;
    }

    const float*  fb = fs + rg * 8;
    const float4* wp = (const float4*)(W) + cg;

    #pragma unroll 4
    for (int k = 0; k < KOUT; k++) {
        int ksrc = (k < 64) ? k : (k + 64);       // skip mx block (folded in bb)
        const float* base = fb + k * ROWS_O;
        ull a0 = *(const ull*)(base);
        ull a1 = *(const ull*)(base + 2);
        ull a2 = *(const ull*)(base + 4);
        ull a3 = *(const ull*)(base + 6);
        float4 w4 = __ldg(wp + (size_t)ksrc * 32);
        ull w0 = pack2(w4.x, w4.x), w1 = pack2(w4.y, w4.y);
        ull w2 = pack2(w4.z, w4.z), w3 = pack2(w4.w, w4.w);
        fma2(acc[0][0], a0, w0); fma2(acc[1][0], a1, w0); fma2(acc[2][0], a2, w0); fma2(acc[3][0], a3, w0);
        fma2(acc[0][1], a0, w1); fma2(acc[1][1], a1, w1); fma2(acc[2][1], a2, w1); fma2(acc[3][1], a3, w1);
        fma2(acc[0][2], a0, w2); fma2(acc[1][2], a1, w2); fma2(acc[2][2], a2, w2); fma2(acc[3][2], a3, w2);
        fma2(acc[0][3], a0, w3); fma2(acc[1][3], a1, w3); fma2(acc[2][3], a2, w3); fma2(acc[3][3], a3, w3);
    }

    #pragma unroll
    for (int rp = 0; rp < 4; rp++) {
        float lo0, hi0, lo1, hi1, lo2, hi2, lo3, hi3;
        unpack2(acc[rp][0], lo0, hi0);
        unpack2(acc[rp][1], lo1, hi1);
        unpack2(acc[rp][2], lo2, hi2);
        unpack2(acc[rp][3], lo3, hi3);
        float4 o0, o1;
        o0.x = fmaxf(lo0, 0.f); o0.y = fmaxf(lo1, 0.f);
        o0.z = fmaxf(lo2, 0.f); o0.w = fmaxf(lo3, 0.f);
        o1.x = fmaxf(hi0, 0.f); o1.y = fmaxf(hi1, 0.f);
        o1.z = fmaxf(hi2, 0.f); o1.w = fmaxf(hi3, 0.f);
        int r0 = bv0 + rg * 8 + rp * 2;
        *(float4*)(out + (size_t)r0 * NOUT + cg * 4)       = o0;
        *(float4*)(out + (size_t)(r0 + 1) * NOUT + cg * 4) = o1;
    }
}

// ---------------- launch ------------------------------------------------------
extern "C" void kernel_launch(void* const* d_in, const int* in_sizes, int n_in,
                              void* d_out, int out_size) {
    const float* x     = (const float*)d_in[0];
    const float* W_slr = (const float*)d_in[1];
    const float* b_slr = (const float*)d_in[2];
    const float* W_out = (const float*)d_in[3];
    const float* b_out = (const float*)d_in[4];
    float* out = (float*)d_out;

    static bool attr_done = false;
    if (!attr_done) {
        cudaFuncSetAttribute(k_front, cudaFuncAttributeMaxDynamicSharedMemorySize, KF_SMEM);
        cudaFuncSetAttribute(k_agg,   cudaFuncAttributeMaxDynamicSharedMemorySize, KA_SMEM);
        cudaFuncSetAttribute(k_out,   cudaFuncAttributeMaxDynamicSharedMemorySize, KO_SMEM);
        attr_done = true;
    }

    k_front<<<BB, 256, KF_SMEM>>>(x, W_slr, b_slr, W_out, b_out);
    k_sel  <<<BB * VV / 8, 256>>>();
    k_agg  <<<BB * 4, 256, KA_SMEM>>>();
    k_out  <<<BB * VV / ROWS_O, 128, KO_SMEM>>>(W_out, out);
}